// round 1
// baseline (speedup 1.0000x reference)
#include <cuda_runtime.h>
#include <cstdint>

// Problem constants (fixed by the reference)
#define ROWS 131072
#define COLS 256
#define NM   128            // num_masked = COLS * 0.5
#define WARPS_PER_BLOCK 8
#define THREADS (WARPS_PER_BLOCK * 32)

// One warp per row.
//  - perm row: permutation of 0..255. First 128 entries = masked set.
//  - masked_indices  = masked set in ascending order
//  - unmasked_indices = complement in ascending order
//  - unmasked_data   = x gathered at unmasked_indices
//  - masked_data     = zeros
// Output buffer = concat(masked_data, masked_indices, unmasked_data,
//                        unmasked_indices), each [ROWS, 128] row-major, f32.
__global__ void __launch_bounds__(THREADS)
masker_kernel(const float* __restrict__ x,
              const int*   __restrict__ perm,
              float* __restrict__ out) {
    const int warp_id = threadIdx.x >> 5;
    const int lane    = threadIdx.x & 31;
    const int row     = blockIdx.x * WARPS_PER_BLOCK + warp_id;

    __shared__ int member[WARPS_PER_BLOCK][COLS];
    int* mem = member[warp_id];

    // Zero membership table (conflict-free: consecutive ints per lane stride)
#pragma unroll
    for (int k = 0; k < 8; k++) mem[lane + 32 * k] = 0;
    __syncwarp();

    // Load the masked half of the permutation: elements [4*lane, 4*lane+4)
    // (lanes 0..31 cover indices 0..127). Vectorized 16B loads, coalesced.
    const int4* prow = reinterpret_cast<const int4*>(perm + (size_t)row * COLS);
    int4 mh = prow[lane];
    // Scatter membership (values are distinct -> no atomics needed)
    mem[mh.x] = 1;
    mem[mh.y] = 1;
    mem[mh.z] = 1;
    mem[mh.w] = 1;
    __syncwarp();

    // Build 256-bit membership mask as 8 ballot words.
    // mask[w] bit l <=> column (32*w + l) is masked.
    unsigned mask[8];
#pragma unroll
    for (int w = 0; w < 8; w++) {
        mask[w] = __ballot_sync(0xffffffffu, mem[32 * w + lane] != 0);
    }

    // Prefix popcount across words
    int base[8];
    int acc = 0;
#pragma unroll
    for (int w = 0; w < 8; w++) {
        base[w] = acc;
        acc += __popc(mask[w]);
    }

    const size_t seg = (size_t)ROWS * NM;   // elements per output array
    float* masked_data   = out;
    float* masked_idx    = out + seg;
    float* unmasked_data = out + 2 * seg;
    float* unmasked_idx  = out + 3 * seg;

    // masked_data row = zeros, coalesced float4 (32 lanes * 4 = 128 floats)
    float4 z = make_float4(0.f, 0.f, 0.f, 0.f);
    reinterpret_cast<float4*>(masked_data + (size_t)row * NM)[lane] = z;

    const float* xrow = x + (size_t)row * COLS;
    float* mi = masked_idx    + (size_t)row * NM;
    float* ud = unmasked_data + (size_t)row * NM;
    float* ui = unmasked_idx  + (size_t)row * NM;

#pragma unroll
    for (int w = 0; w < 8; w++) {
        const int c = 32 * w + lane;
        const unsigned below = mask[w] & ((1u << lane) - 1u);
        const int mrank = base[w] + __popc(below);  // # masked cols < c
        if ((mask[w] >> lane) & 1u) {
            mi[mrank] = (float)c;
        } else {
            const int urank = c - mrank;            // # unmasked cols < c
            ud[urank] = xrow[c];
            ui[urank] = (float)c;
        }
    }
}

extern "C" void kernel_launch(void* const* d_in, const int* in_sizes, int n_in,
                              void* d_out, int out_size) {
    const float* x    = (const float*)d_in[0];
    const int*   perm = (const int*)d_in[1];
    float* out = (float*)d_out;

    const int blocks = ROWS / WARPS_PER_BLOCK;  // 16384
    masker_kernel<<<blocks, THREADS>>>(x, perm, out);
}

// round 2
// speedup vs baseline: 1.0558x; 1.0558x over previous
#include <cuda_runtime.h>
#include <cstdint>

#define ROWS 131072
#define COLS 256
#define NM   128
#define WPB  8                    // warps per block (one row per warp)
#define THREADS (WPB * 32)

// Output = concat(masked_data, masked_indices, unmasked_data, unmasked_indices),
// each [ROWS, 128] row-major f32.
__global__ void __launch_bounds__(THREADS)
masker_kernel(const float* __restrict__ x,
              const int*   __restrict__ perm,
              float* __restrict__ out) {
    const int warp_id = threadIdx.x >> 5;
    const int lane    = threadIdx.x & 31;
    const int row     = blockIdx.x * WPB + warp_id;

    // Per-warp scratch: 256 ints (membership), later reused as 256-float x stage.
    __shared__ int   member[WPB][COLS];
    // Per-warp output stage: [mi | ud | ui], 3*128 floats.
    __shared__ float stage[WPB][3 * NM];

    int* mem = member[warp_id];

    // --- membership ---
#pragma unroll
    for (int k = 0; k < 8; k++) mem[lane + 32 * k] = 0;
    __syncwarp();

    // masked half of the permutation (first 128 entries), coalesced int4
    const int4* prow = reinterpret_cast<const int4*>(perm + (size_t)row * COLS);
    int4 mh = prow[lane];
    mem[mh.x] = 1;
    mem[mh.y] = 1;
    mem[mh.z] = 1;
    mem[mh.w] = 1;
    __syncwarp();

    unsigned mask[8];
#pragma unroll
    for (int w = 0; w < 8; w++)
        mask[w] = __ballot_sync(0xffffffffu, mem[32 * w + lane] != 0);

    int base[8];
    int acc = 0;
#pragma unroll
    for (int w = 0; w < 8; w++) { base[w] = acc; acc += __popc(mask[w]); }

    // --- stage x row in shared (reuse membership storage; dead after ballots) ---
    float* xbuf = reinterpret_cast<float*>(mem);
    const float4* xrow4 = reinterpret_cast<const float4*>(x + (size_t)row * COLS);
    float4 xa = xrow4[lane];        // floats [4*lane, 4*lane+4)
    float4 xb = xrow4[lane + 32];   // floats [128 + 4*lane, ...)
    reinterpret_cast<float4*>(xbuf)[lane]      = xa;
    reinterpret_cast<float4*>(xbuf)[lane + 32] = xb;

    float* smi = stage[warp_id];
    float* sud = stage[warp_id] + NM;
    float* sui = stage[warp_id] + 2 * NM;
    __syncwarp();

    // --- rank + scatter into shared stage ---
#pragma unroll
    for (int w = 0; w < 8; w++) {
        const int c = 32 * w + lane;
        const unsigned below = mask[w] & ((1u << lane) - 1u);
        const int mrank = base[w] + __popc(below);      // # masked < c
        if ((mask[w] >> lane) & 1u) {
            smi[mrank] = (float)c;
        } else {
            const int urank = c - mrank;                // # unmasked < c
            sud[urank] = xbuf[c];
            sui[urank] = (float)c;
        }
    }
    __syncwarp();

    // --- coalesced write-out ---
    const size_t seg = (size_t)ROWS * NM;
    float4* o_md = reinterpret_cast<float4*>(out + (size_t)row * NM);
    float4* o_mi = reinterpret_cast<float4*>(out + seg     + (size_t)row * NM);
    float4* o_ud = reinterpret_cast<float4*>(out + 2 * seg + (size_t)row * NM);
    float4* o_ui = reinterpret_cast<float4*>(out + 3 * seg + (size_t)row * NM);

    o_md[lane] = make_float4(0.f, 0.f, 0.f, 0.f);
    o_mi[lane] = reinterpret_cast<float4*>(smi)[lane];
    o_ud[lane] = reinterpret_cast<float4*>(sud)[lane];
    o_ui[lane] = reinterpret_cast<float4*>(sui)[lane];
}

extern "C" void kernel_launch(void* const* d_in, const int* in_sizes, int n_in,
                              void* d_out, int out_size) {
    const float* x    = (const float*)d_in[0];
    const int*   perm = (const int*)d_in[1];
    float* out = (float*)d_out;

    masker_kernel<<<ROWS / WPB, THREADS>>>(x, perm, out);
}